// round 5
// baseline (speedup 1.0000x reference)
#include <cuda_runtime.h>

#define B_ 1024
#define F_ 512
#define H_ 1024
#define S_ 8
#define BOX_ 12
#define MAXB_ 64
#define MAXSY_ 64
#define L_ 126
#define G_ 256
#define NT_ 256
#define NGRP 16
#define GBLK 16          // blocks per group
#define BK 16
#define AST 68           // As row stride (floats): 64 + pad (272B = 17*16)
#define WST 132          // Ws row stride (floats): 128 dup + pad (528B = 33*16)

__device__ float g_stack[4][B_ * F_];
__device__ float g_h[B_ * H_];
__device__ float g_box[MAXB_][B_ * BOX_];
__device__ float g_sym[MAXSY_][B_ * S_];

struct Bar { unsigned cnt; unsigned gen; unsigned pad[30]; };
__device__ Bar g_gbar[NGRP];   // group-local barriers
__device__ Bar g_abar;         // global barrier (emit)

typedef unsigned long long u64;

__device__ __forceinline__ void ffma2(u64& d, u64 a, u64 b) {
    asm("fma.rn.f32x2 %0,%1,%2,%0;" : "+l"(d) : "l"(a), "l"(b));
}
__device__ __forceinline__ float2 up2(u64 v) {
    float2 r; asm("mov.b64 {%0,%1},%2;" : "=f"(r.x), "=f"(r.y) : "l"(v)); return r;
}
// tanh(x) = 1 - 2/(e^{2x}+1): exact identity, only MUFU rounding (~1e-6 rel)
__device__ __forceinline__ float fast_tanh(float x) {
    float e, r;
    asm("ex2.approx.f32 %0,%1;" : "=f"(e) : "f"(x * 2.8853900817779268f));
    asm("rcp.approx.f32 %0,%1;" : "=f"(r) : "f"(e + 1.0f));
    return fmaf(-2.0f, r, 1.0f);
}

// n-arrival inter-block barrier (all participating blocks resident)
__device__ __forceinline__ void barrier_n(Bar* b, unsigned n) {
    __syncthreads();
    if (threadIdx.x == 0) {
        volatile unsigned* gen = &b->gen;
        unsigned g = *gen;
        __threadfence();                       // release
        if (atomicAdd(&b->cnt, 1u) == n - 1u) {
            b->cnt = 0;
            __threadfence();
            *gen = g + 1u;
        } else {
            while (*gen == g) { __nanosleep(32); }
        }
        __threadfence();                       // acquire (invalidate stale L1)
    }
    __syncthreads();
}

// C[m0..+64, n0..+64) = tanh(A·Wᵀ + bias). A:[MxK], W:[Nv x K] row-major.
// 256 threads, 8m x 2n microtile, f32x2 accumulators, dup'd W, double buffer.
__device__ __noinline__ void gemm_tile(
    const float* __restrict__ A, const float* __restrict__ W,
    const float* __restrict__ bias, float* __restrict__ C,
    int K, int Nv, int ldc, int m0, int n0)
{
    __shared__ __align__(16) float As[2][BK][AST];
    __shared__ __align__(16) float Ws[2][BK][WST];

    const int tid = threadIdx.x;
    const int mA0 = (tid & 7) * 4;     // m rows mA0..+3 and mA0+32..+35
    const int tn0 = (tid >> 3) * 2;    // 2 n columns

    const int lr = tid >> 2;           // loader row 0..63
    const int kq = (tid & 3) * 4;      // loader k offset 0,4,8,12
    const float* Ap = A + (size_t)(m0 + lr) * K + kq;
    const bool wv = (n0 + lr) < Nv;
    const float* Wp = W + (size_t)(n0 + lr) * K + kq;

    u64 acc[2][4];
#pragma unroll
    for (int j = 0; j < 2; ++j)
#pragma unroll
        for (int p = 0; p < 4; ++p) acc[j][p] = 0ull;

    float4 a = *(const float4*)Ap;
    float4 w = wv ? *(const float4*)Wp : make_float4(0.f, 0.f, 0.f, 0.f);

    As[0][kq+0][lr]=a.x; As[0][kq+1][lr]=a.y; As[0][kq+2][lr]=a.z; As[0][kq+3][lr]=a.w;
    *(float2*)&Ws[0][kq+0][2*lr]=make_float2(w.x,w.x);
    *(float2*)&Ws[0][kq+1][2*lr]=make_float2(w.y,w.y);
    *(float2*)&Ws[0][kq+2][2*lr]=make_float2(w.z,w.z);
    *(float2*)&Ws[0][kq+3][2*lr]=make_float2(w.w,w.w);
    __syncthreads();

    const int P = K / BK;
    for (int p = 0; p < P; ++p) {
        const int cur = p & 1;
        const bool more = (p + 1) < P;
        if (more) {
            a = *(const float4*)(Ap + (p + 1) * BK);
            w = wv ? *(const float4*)(Wp + (p + 1) * BK) : make_float4(0.f,0.f,0.f,0.f);
        }
#pragma unroll
        for (int k = 0; k < BK; ++k) {
            ulonglong2 x0 = *(const ulonglong2*)&As[cur][k][mA0];
            ulonglong2 x1 = *(const ulonglong2*)&As[cur][k][mA0 + 32];
            ulonglong2 y  = *(const ulonglong2*)&Ws[cur][k][2 * tn0];
            ffma2(acc[0][0], x0.x, y.x); ffma2(acc[0][1], x0.y, y.x);
            ffma2(acc[0][2], x1.x, y.x); ffma2(acc[0][3], x1.y, y.x);
            ffma2(acc[1][0], x0.x, y.y); ffma2(acc[1][1], x0.y, y.y);
            ffma2(acc[1][2], x1.x, y.y); ffma2(acc[1][3], x1.y, y.y);
        }
        if (more) {
            const int nb = cur ^ 1;
            As[nb][kq+0][lr]=a.x; As[nb][kq+1][lr]=a.y;
            As[nb][kq+2][lr]=a.z; As[nb][kq+3][lr]=a.w;
            *(float2*)&Ws[nb][kq+0][2*lr]=make_float2(w.x,w.x);
            *(float2*)&Ws[nb][kq+1][2*lr]=make_float2(w.y,w.y);
            *(float2*)&Ws[nb][kq+2][2*lr]=make_float2(w.z,w.z);
            *(float2*)&Ws[nb][kq+3][2*lr]=make_float2(w.w,w.w);
        }
        __syncthreads();
    }

    const int col = n0 + tn0;
    if (col < Nv) {
        const float b0 = __ldg(&bias[col]);
        const float b1 = __ldg(&bias[col + 1]);
#pragma unroll
        for (int p2 = 0; p2 < 4; ++p2) {
            const int r = m0 + ((p2 < 2) ? (mA0 + 2 * p2) : (mA0 + 32 + 2 * (p2 - 2)));
            float2 v0 = up2(acc[0][p2]);
            float2 v1 = up2(acc[1][p2]);
            *(float2*)&C[(size_t)r * ldc + col] =
                make_float2(fast_tanh(v0.x + b0), fast_tanh(v1.x + b1));
            *(float2*)&C[(size_t)(r + 1) * ldc + col] =
                make_float2(fast_tanh(v0.y + b0), fast_tanh(v1.y + b1));
        }
    }
}

__global__ __launch_bounds__(NT_, 2)
void k_persist(const float* __restrict__ x, const int* __restrict__ ops,
               const float* __restrict__ Wd,  const float* __restrict__ bd,
               const float* __restrict__ Wl,  const float* __restrict__ bl,
               const float* __restrict__ Wr,  const float* __restrict__ br,
               const float* __restrict__ Wsd, const float* __restrict__ bsd,
               const float* __restrict__ Wsf, const float* __restrict__ bsf,
               const float* __restrict__ Wss, const float* __restrict__ bss,
               const float* __restrict__ Wbox,const float* __restrict__ bbox,
               float* __restrict__ out)
{
    const int gid = blockIdx.x >> 4;       // group 0..15 (64 batch rows each)
    const int lid = blockIdx.x & 15;       // block within group
    const int m_grp = gid * 64;
    Bar* gb = &g_gbar[gid];

    // init this group's stack plane 0
    for (int i = lid * NT_ + threadIdx.x; i < 64 * F_; i += GBLK * NT_)
        g_stack[0][m_grp * F_ + i] = x[m_grp * F_ + i];
    barrier_n(gb, GBLK);

    int sp = 1, bc = 0, sc = 0;
    for (int t = 0; t < L_; ++t) {
        const int op = __ldg(&ops[L_ - 1 - t]);   // processing order (row 0)
        if (op == 1) {
            gemm_tile(g_stack[sp - 1], Wd, bd, g_h, F_, H_, H_, m_grp, lid * 64);
            barrier_n(gb, GBLK);
            if (lid < 8)
                gemm_tile(g_h, Wl, bl, g_stack[sp - 1], H_, F_, F_, m_grp, lid * 64);
            else
                gemm_tile(g_h, Wr, br, g_stack[sp], H_, F_, F_, m_grp, (lid - 8) * 64);
            barrier_n(gb, GBLK);
            ++sp;
        } else if (op == 2) {
            gemm_tile(g_stack[sp - 1], Wsd, bsd, g_h, F_, H_, H_, m_grp, lid * 64);
            barrier_n(gb, GBLK);
            if (lid < 8)
                gemm_tile(g_h, Wsf, bsf, g_stack[sp - 1], H_, F_, F_, m_grp, lid * 64);
            else if (lid == 8)
                gemm_tile(g_h, Wss, bss, g_sym[sc], H_, S_, S_, m_grp, 0);
            barrier_n(gb, GBLK);
            ++sc;
        } else {
            // pop: box[bc] = tanh(Wbox·top + bbox). 8 warps: 2 per row, 4 rows.
            const int wp = threadIdx.x >> 5, lane = threadIdx.x & 31;
            const int row = m_grp + lid * 4 + (wp >> 1);
            const float* tr = g_stack[sp - 1] + (size_t)row * F_;
            float xv[F_ / 32];
#pragma unroll
            for (int i = 0; i < F_ / 32; ++i) xv[i] = tr[lane + 32 * i];
            for (int c = (wp & 1); c < BOX_; c += 2) {
                const float* wr = Wbox + (size_t)c * F_;
                float s = 0.f;
#pragma unroll
                for (int i = 0; i < F_ / 32; ++i)
                    s = fmaf(xv[i], __ldg(&wr[lane + 32 * i]), s);
#pragma unroll
                for (int off = 16; off > 0; off >>= 1)
                    s += __shfl_xor_sync(0xffffffffu, s, off);
                if (lane == 0)
                    g_box[bc][row * BOX_ + c] = fast_tanh(s + __ldg(&bbox[c]));
            }
            ++bc; --sp;   // no barrier: box read only after final global barrier
        }
    }

    barrier_n(&g_abar, G_);   // all groups done

    // emit: boxes [B,64,12] then syms [B,64,8], reversed + zero-padded
    const int NBOX = B_ * MAXB_ * BOX_;
    const int NSYM = B_ * MAXSY_ * S_;
    for (int idx = blockIdx.x * NT_ + threadIdx.x; idx < NBOX + NSYM; idx += G_ * NT_) {
        if (idx < NBOX) {
            int b = idx / (MAXB_ * BOX_);
            int r = idx % (MAXB_ * BOX_);
            int j = r / BOX_, c = r % BOX_;
            out[idx] = (j < bc) ? g_box[bc - 1 - j][b * BOX_ + c] : 0.f;
        } else {
            int i2 = idx - NBOX;
            int b = i2 / (MAXSY_ * S_);
            int r = i2 % (MAXSY_ * S_);
            int j = r / S_, c = r % S_;
            out[idx] = (j < sc) ? g_sym[sc - 1 - j][b * S_ + c] : 0.f;
        }
    }
}

extern "C" void kernel_launch(void* const* d_in, const int* in_sizes, int n_in,
                              void* d_out, int out_size) {
    (void)in_sizes; (void)n_in; (void)out_size;
    k_persist<<<G_, NT_>>>(
        (const float*)d_in[0], (const int*)d_in[1],
        (const float*)d_in[2], (const float*)d_in[3],
        (const float*)d_in[4], (const float*)d_in[5],
        (const float*)d_in[6], (const float*)d_in[7],
        (const float*)d_in[8], (const float*)d_in[9],
        (const float*)d_in[10], (const float*)d_in[11],
        (const float*)d_in[12], (const float*)d_in[13],
        (const float*)d_in[14], (const float*)d_in[15],
        (float*)d_out);
}

// round 6
// speedup vs baseline: 1.2705x; 1.2705x over previous
#include <cuda_runtime.h>

#define B_ 1024
#define F_ 512
#define H_ 1024
#define S_ 8
#define BOX_ 12
#define MAXB_ 64
#define MAXSY_ 64
#define L_ 126
#define G_ 256
#define NT_ 256
#define BK 16
#define AST 68     // As row stride (floats): 64 + pad (272B = 17*16)
#define WST 132    // Ws row stride (floats): 128 dup + pad (528B = 33*16)

__device__ float g_stack[4][B_ * F_];
__device__ float g_h[B_ * H_];
__device__ float g_box[MAXB_][B_ * BOX_];
__device__ float g_sym[MAXSY_][B_ * S_];
__device__ unsigned g_cnt = 0;
__device__ unsigned g_gen = 0;

typedef unsigned long long u64;

__device__ __forceinline__ void ffma2(u64& d, u64 a, u64 b) {
    asm("fma.rn.f32x2 %0,%1,%2,%0;" : "+l"(d) : "l"(a), "l"(b));
}
__device__ __forceinline__ float2 up2(u64 v) {
    float2 r; asm("mov.b64 {%0,%1},%2;" : "=f"(r.x), "=f"(r.y) : "l"(v)); return r;
}
// tanh(x) = 1 - 2/(e^{2x}+1): exact identity, only MUFU rounding (~1e-6 rel)
__device__ __forceinline__ float fast_tanh(float x) {
    float e, r;
    asm("ex2.approx.f32 %0,%1;" : "=f"(e) : "f"(x * 2.8853900817779268f));
    asm("rcp.approx.f32 %0,%1;" : "=f"(r) : "f"(e + 1.0f));
    return fmaf(-2.0f, r, 1.0f);
}

// grid barrier: all G_ blocks resident (256 thr, 2 blocks/SM -> 296 slots >= 256)
__device__ __forceinline__ void gsync() {
    __syncthreads();
    if (threadIdx.x == 0) {
        volatile unsigned* gen = &g_gen;
        unsigned g = *gen;
        __threadfence();                      // release
        if (atomicAdd(&g_cnt, 1u) == G_ - 1u) {
            g_cnt = 0;
            __threadfence();
            *gen = g + 1u;
        } else {
            while (*gen == g) { __nanosleep(64); }
        }
        __threadfence();                      // acquire (invalidate stale L1)
    }
    __syncthreads();
}

// C[m0..+64, n0..+64) = tanh(A·Wᵀ + bias). A:[MxK], W:[Nv x K] row-major.
// 256 threads, 4m(paired)x4n microtile, dup'd W in smem, double-buffered.
__device__ __noinline__ void gemm_tile(
    const float* __restrict__ A, const float* __restrict__ W,
    const float* __restrict__ bias, float* __restrict__ C,
    int K, int Nv, int ldc, int m0, int n0)
{
    __shared__ __align__(16) float As[2][BK][AST];
    __shared__ __align__(16) float Ws[2][BK][WST];

    const int tid = threadIdx.x;
    const int tm0 = (tid & 15) * 4;    // 4 m rows (2 f32x2 pairs)
    const int tn0 = (tid >> 4) * 4;    // 4 n cols

    const int lr = tid >> 2;           // loader row 0..63
    const int kq = (tid & 3) * 4;      // loader k offset 0,4,8,12
    const float* Ap = A + (size_t)(m0 + lr) * K + kq;
    const bool wv = (n0 + lr) < Nv;
    const float* Wp = W + (size_t)(n0 + lr) * K + kq;

    u64 acc[4][2];                     // [n][m-pair]
#pragma unroll
    for (int j = 0; j < 4; ++j) { acc[j][0] = 0ull; acc[j][1] = 0ull; }

    float4 a = *(const float4*)Ap;
    float4 w = wv ? *(const float4*)Wp : make_float4(0.f, 0.f, 0.f, 0.f);

    As[0][kq+0][lr]=a.x; As[0][kq+1][lr]=a.y; As[0][kq+2][lr]=a.z; As[0][kq+3][lr]=a.w;
    *(float2*)&Ws[0][kq+0][2*lr]=make_float2(w.x,w.x);
    *(float2*)&Ws[0][kq+1][2*lr]=make_float2(w.y,w.y);
    *(float2*)&Ws[0][kq+2][2*lr]=make_float2(w.z,w.z);
    *(float2*)&Ws[0][kq+3][2*lr]=make_float2(w.w,w.w);
    __syncthreads();

    const int P = K / BK;
    for (int p = 0; p < P; ++p) {
        const int cur = p & 1;
        const bool more = (p + 1) < P;
        if (more) {    // global prefetch of next panel into registers
            a = *(const float4*)(Ap + (p + 1) * BK);
            w = wv ? *(const float4*)(Wp + (p + 1) * BK) : make_float4(0.f,0.f,0.f,0.f);
        }
#pragma unroll
        for (int k = 0; k < BK; ++k) {
            ulonglong2 x  = *(const ulonglong2*)&As[cur][k][tm0];
            ulonglong2 y0 = *(const ulonglong2*)&Ws[cur][k][2 * tn0];
            ulonglong2 y1 = *(const ulonglong2*)&Ws[cur][k][2 * tn0 + 4];
            ffma2(acc[0][0], x.x, y0.x); ffma2(acc[0][1], x.y, y0.x);
            ffma2(acc[1][0], x.x, y0.y); ffma2(acc[1][1], x.y, y0.y);
            ffma2(acc[2][0], x.x, y1.x); ffma2(acc[2][1], x.y, y1.x);
            ffma2(acc[3][0], x.x, y1.y); ffma2(acc[3][1], x.y, y1.y);
        }
        if (more) {
            const int nb = cur ^ 1;
            As[nb][kq+0][lr]=a.x; As[nb][kq+1][lr]=a.y;
            As[nb][kq+2][lr]=a.z; As[nb][kq+3][lr]=a.w;
            *(float2*)&Ws[nb][kq+0][2*lr]=make_float2(w.x,w.x);
            *(float2*)&Ws[nb][kq+1][2*lr]=make_float2(w.y,w.y);
            *(float2*)&Ws[nb][kq+2][2*lr]=make_float2(w.z,w.z);
            *(float2*)&Ws[nb][kq+3][2*lr]=make_float2(w.w,w.w);
        }
        __syncthreads();
    }

    // epilogue: bias + tanh; paired STG.64 along n (cols even-aligned, Nv even)
#pragma unroll
    for (int jj = 0; jj < 4; jj += 2) {
        const int col = n0 + tn0 + jj;
        if (col < Nv) {
            const float b0 = __ldg(&bias[col]);
            const float b1 = __ldg(&bias[col + 1]);
#pragma unroll
            for (int p2 = 0; p2 < 2; ++p2) {
                const int r = m0 + tm0 + 2 * p2;
                float2 vj = up2(acc[jj][p2]);
                float2 vk = up2(acc[jj + 1][p2]);
                *(float2*)&C[(size_t)r * ldc + col] =
                    make_float2(fast_tanh(vj.x + b0), fast_tanh(vk.x + b1));
                *(float2*)&C[(size_t)(r + 1) * ldc + col] =
                    make_float2(fast_tanh(vj.y + b0), fast_tanh(vk.y + b1));
            }
        }
    }
}

__global__ __launch_bounds__(NT_, 2)
void k_persist(const float* __restrict__ x, const int* __restrict__ ops,
               const float* __restrict__ Wd,  const float* __restrict__ bd,
               const float* __restrict__ Wl,  const float* __restrict__ bl,
               const float* __restrict__ Wr,  const float* __restrict__ br,
               const float* __restrict__ Wsd, const float* __restrict__ bsd,
               const float* __restrict__ Wsf, const float* __restrict__ bsf,
               const float* __restrict__ Wss, const float* __restrict__ bss,
               const float* __restrict__ Wbox,const float* __restrict__ bbox,
               float* __restrict__ out)
{
    const int id = blockIdx.x;
    for (int i = id * NT_ + threadIdx.x; i < B_ * F_; i += G_ * NT_)
        g_stack[0][i] = x[i];
    gsync();

    int sp = 1, bc = 0, sc = 0;
    for (int t = 0; t < L_; ++t) {
        const int op = __ldg(&ops[L_ - 1 - t]);   // processing order (row 0)
        if (op == 1) {
            gemm_tile(g_stack[sp - 1], Wd, bd, g_h, F_, H_, H_,
                      (id >> 4) * 64, (id & 15) * 64);
            gsync();
            if (id < 128)
                gemm_tile(g_h, Wl, bl, g_stack[sp - 1], H_, F_, F_,
                          (id >> 3) * 64, (id & 7) * 64);
            else
                gemm_tile(g_h, Wr, br, g_stack[sp], H_, F_, F_,
                          ((id - 128) >> 3) * 64, ((id - 128) & 7) * 64);
            gsync();
            ++sp;
        } else if (op == 2) {
            gemm_tile(g_stack[sp - 1], Wsd, bsd, g_h, F_, H_, H_,
                      (id >> 4) * 64, (id & 15) * 64);
            gsync();
            if (id < 128)
                gemm_tile(g_h, Wsf, bsf, g_stack[sp - 1], H_, F_, F_,
                          (id >> 3) * 64, (id & 7) * 64);
            else if (id < 144)
                gemm_tile(g_h, Wss, bss, g_sym[sc], H_, S_, S_,
                          (id - 128) * 64, 0);
            gsync();
            ++sc;
        } else {
            // pop: box[bc] = tanh(Wbox·top + bbox). 8 warps: 2 per row, 4 rows.
            const int wp = threadIdx.x >> 5, lane = threadIdx.x & 31;
            const int row = id * 4 + (wp >> 1);
            const float* tr = g_stack[sp - 1] + (size_t)row * F_;
            float xv[F_ / 32];
#pragma unroll
            for (int i = 0; i < F_ / 32; ++i) xv[i] = tr[lane + 32 * i];
            for (int c = (wp & 1); c < BOX_; c += 2) {
                const float* wr = Wbox + (size_t)c * F_;
                float s = 0.f;
#pragma unroll
                for (int i = 0; i < F_ / 32; ++i)
                    s = fmaf(xv[i], __ldg(&wr[lane + 32 * i]), s);
#pragma unroll
                for (int off = 16; off > 0; off >>= 1)
                    s += __shfl_xor_sync(0xffffffffu, s, off);
                if (lane == 0)
                    g_box[bc][row * BOX_ + c] = fast_tanh(s + __ldg(&bbox[c]));
            }
            ++bc; --sp;   // next phase's gsync orders these writes before emit
        }
    }
    gsync();

    // emit: boxes [B,64,12] then syms [B,64,8], reversed + zero-padded
    const int NBOX = B_ * MAXB_ * BOX_;
    const int NSYM = B_ * MAXSY_ * S_;
    for (int idx = id * NT_ + threadIdx.x; idx < NBOX + NSYM; idx += G_ * NT_) {
        if (idx < NBOX) {
            int b = idx / (MAXB_ * BOX_);
            int r = idx % (MAXB_ * BOX_);
            int j = r / BOX_, c = r % BOX_;
            out[idx] = (j < bc) ? g_box[bc - 1 - j][b * BOX_ + c] : 0.f;
        } else {
            int i2 = idx - NBOX;
            int b = i2 / (MAXSY_ * S_);
            int r = i2 % (MAXSY_ * S_);
            int j = r / S_, c = r % S_;
            out[idx] = (j < sc) ? g_sym[sc - 1 - j][b * S_ + c] : 0.f;
        }
    }
}

extern "C" void kernel_launch(void* const* d_in, const int* in_sizes, int n_in,
                              void* d_out, int out_size) {
    (void)in_sizes; (void)n_in; (void)out_size;
    k_persist<<<G_, NT_>>>(
        (const float*)d_in[0], (const int*)d_in[1],
        (const float*)d_in[2], (const float*)d_in[3],
        (const float*)d_in[4], (const float*)d_in[5],
        (const float*)d_in[6], (const float*)d_in[7],
        (const float*)d_in[8], (const float*)d_in[9],
        (const float*)d_in[10], (const float*)d_in[11],
        (const float*)d_in[12], (const float*)d_in[13],
        (const float*)d_in[14], (const float*)d_in[15],
        (float*)d_out);
}

// round 7
// speedup vs baseline: 1.4922x; 1.1745x over previous
#include <cuda_runtime.h>

#define B_ 1024
#define F_ 512
#define H_ 1024
#define S_ 8
#define BOX_ 12
#define MAXB_ 64
#define MAXSY_ 64
#define L_ 126
#define G_ 256
#define NT_ 256
#define BKH 8      // k per panel per half
#define AST 68     // As row stride (floats)
#define WST 132    // Ws row stride (floats), duplicated 128 + pad

__device__ float g_stack[4][B_ * F_];
__device__ float g_h[B_ * H_];
__device__ float g_box[MAXB_][B_ * BOX_];
__device__ float g_sym[MAXSY_][B_ * S_];
__device__ unsigned g_leaf[16];
__device__ unsigned g_root = 0;
__device__ volatile unsigned g_gen = 0;

typedef unsigned long long u64;

__device__ __forceinline__ void ffma2(u64& d, u64 a, u64 b) {
    asm("fma.rn.f32x2 %0,%1,%2,%0;" : "+l"(d) : "l"(a), "l"(b));
}
__device__ __forceinline__ u64 fadd2(u64 a, u64 b) {
    u64 r; asm("add.rn.f32x2 %0,%1,%2;" : "=l"(r) : "l"(a), "l"(b)); return r;
}
__device__ __forceinline__ float2 up2(u64 v) {
    float2 r; asm("mov.b64 {%0,%1},%2;" : "=f"(r.x), "=f"(r.y) : "l"(v)); return r;
}
// tanh(x) = 1 - 2/(e^{2x}+1): exact identity, only MUFU rounding (~1e-6 rel)
__device__ __forceinline__ float fast_tanh(float x) {
    float e, r;
    asm("ex2.approx.f32 %0,%1;" : "=f"(e) : "f"(x * 2.8853900817779268f));
    asm("rcp.approx.f32 %0,%1;" : "=f"(r) : "f"(e + 1.0f));
    return fmaf(-2.0f, r, 1.0f);
}

// two-level grid barrier: 16 leaves + root (all 256 blocks resident)
__device__ __forceinline__ void gsync() {
    __syncthreads();
    if (threadIdx.x == 0) {
        unsigned g = g_gen;
        __threadfence();                                  // release
        const unsigned l = blockIdx.x & 15u;
        if (atomicAdd(&g_leaf[l], 1u) == 15u) {
            atomicExch(&g_leaf[l], 0u);
            if (atomicAdd(&g_root, 1u) == 15u) {
                atomicExch(&g_root, 0u);
                __threadfence();
                g_gen = g + 1u;
            }
        }
        while (g_gen == g) { __nanosleep(32); }
        __threadfence();                                  // acquire (drop stale L1)
    }
    __syncthreads();
}

// C[m0..+64, n0..+64) = tanh(A·Wᵀ + bias). A:[MxK], W:[Nv x K] row-major.
// 256 threads = 2 K-halves x 128 threads; per-half microtile 8m x 4n,
// f32x2 accum pairs along m, duplicated W in smem (all LDS warp-dedup clean).
__device__ __noinline__ void gemm_tile(
    const float* __restrict__ A, const float* __restrict__ W,
    const float* __restrict__ bias, float* __restrict__ C,
    int K, int Nv, int ldc, int m0, int n0)
{
    __shared__ __align__(16) float As[2][2][BKH][AST];
    __shared__ __align__(16) float Ws[2][2][BKH][WST];

    const int tid  = threadIdx.x;
    const int half = tid >> 7;
    const int ht   = tid & 127;
    const int mA0  = (ht & 7) * 4;      // rows mA0..+3 and mA0+32..+35
    const int tn0  = (ht >> 3) * 4;     // 4 n cols
    const int lr   = ht >> 1;           // loader row 0..63
    const int kq   = (ht & 1) * 4;      // loader k offset 0 or 4
    const int Kh   = K >> 1;
    const int kb   = half * Kh;

    const float* Ap = A + (size_t)(m0 + lr) * K + kb + kq;
    const bool wv = (n0 + lr) < Nv;
    const float* Wp = W + (size_t)(n0 + lr) * K + kb + kq;

    u64 acc[4][4];
#pragma unroll
    for (int j = 0; j < 4; ++j)
#pragma unroll
        for (int p = 0; p < 4; ++p) acc[j][p] = 0ull;

    float4 a = *(const float4*)Ap;
    float4 w = wv ? *(const float4*)Wp : make_float4(0.f, 0.f, 0.f, 0.f);

    As[half][0][kq+0][lr]=a.x; As[half][0][kq+1][lr]=a.y;
    As[half][0][kq+2][lr]=a.z; As[half][0][kq+3][lr]=a.w;
    *(float2*)&Ws[half][0][kq+0][2*lr]=make_float2(w.x,w.x);
    *(float2*)&Ws[half][0][kq+1][2*lr]=make_float2(w.y,w.y);
    *(float2*)&Ws[half][0][kq+2][2*lr]=make_float2(w.z,w.z);
    *(float2*)&Ws[half][0][kq+3][2*lr]=make_float2(w.w,w.w);
    __syncthreads();

    const int Ph = Kh / BKH;
    for (int p = 0; p < Ph; ++p) {
        const int cur = p & 1;
        const bool more = (p + 1) < Ph;
        if (more) {
            a = *(const float4*)(Ap + (p + 1) * BKH);
            w = wv ? *(const float4*)(Wp + (p + 1) * BKH)
                   : make_float4(0.f, 0.f, 0.f, 0.f);
        }
#pragma unroll
        for (int k = 0; k < BKH; ++k) {
            ulonglong2 x0 = *(const ulonglong2*)&As[half][cur][k][mA0];
            ulonglong2 x1 = *(const ulonglong2*)&As[half][cur][k][mA0 + 32];
            ulonglong2 y0 = *(const ulonglong2*)&Ws[half][cur][k][2 * tn0];
            ulonglong2 y1 = *(const ulonglong2*)&Ws[half][cur][k][2 * tn0 + 4];
            ffma2(acc[0][0], x0.x, y0.x); ffma2(acc[0][1], x0.y, y0.x);
            ffma2(acc[0][2], x1.x, y0.x); ffma2(acc[0][3], x1.y, y0.x);
            ffma2(acc[1][0], x0.x, y0.y); ffma2(acc[1][1], x0.y, y0.y);
            ffma2(acc[1][2], x1.x, y0.y); ffma2(acc[1][3], x1.y, y0.y);
            ffma2(acc[2][0], x0.x, y1.x); ffma2(acc[2][1], x0.y, y1.x);
            ffma2(acc[2][2], x1.x, y1.x); ffma2(acc[2][3], x1.y, y1.x);
            ffma2(acc[3][0], x0.x, y1.y); ffma2(acc[3][1], x0.y, y1.y);
            ffma2(acc[3][2], x1.x, y1.y); ffma2(acc[3][3], x1.y, y1.y);
        }
        if (more) {
            const int nb = cur ^ 1;
            As[half][nb][kq+0][lr]=a.x; As[half][nb][kq+1][lr]=a.y;
            As[half][nb][kq+2][lr]=a.z; As[half][nb][kq+3][lr]=a.w;
            *(float2*)&Ws[half][nb][kq+0][2*lr]=make_float2(w.x,w.x);
            *(float2*)&Ws[half][nb][kq+1][2*lr]=make_float2(w.y,w.y);
            *(float2*)&Ws[half][nb][kq+2][2*lr]=make_float2(w.z,w.z);
            *(float2*)&Ws[half][nb][kq+3][2*lr]=make_float2(w.w,w.w);
        }
        __syncthreads();
    }

    // split-K reduce: half 1 stages partials (conflict-free: lane-stride 8B)
    u64* red = (u64*)&Ws[0][0][0][0];   // 16KB needed, 33KB available
    if (half == 1) {
#pragma unroll
        for (int j = 0; j < 4; ++j)
#pragma unroll
            for (int p2 = 0; p2 < 2; ++p2) {
                red[(j * 4 + 2*p2    ) * 128 + ht] = acc[j][2*p2];
                red[(j * 4 + 2*p2 + 1) * 128 + ht] = acc[j][2*p2+1];
            }
    }
    __syncthreads();
    if (half == 0) {
#pragma unroll
        for (int j = 0; j < 4; ++j)
#pragma unroll
            for (int p2 = 0; p2 < 4; ++p2)
                acc[j][p2] = fadd2(acc[j][p2], red[(j * 4 + p2) * 128 + ht]);

        // epilogue: bias + tanh; paired float2 stores along n
#pragma unroll
        for (int jj = 0; jj < 4; jj += 2) {
            const int col = n0 + tn0 + jj;
            if (col < Nv) {
                const float b0 = __ldg(&bias[col]);
                const float b1 = __ldg(&bias[col + 1]);
#pragma unroll
                for (int p2 = 0; p2 < 4; ++p2) {
                    const int r = m0 + ((p2 < 2) ? (mA0 + 2 * p2)
                                                 : (mA0 + 32 + 2 * (p2 - 2)));
                    float2 vj = up2(acc[jj][p2]);
                    float2 vk = up2(acc[jj + 1][p2]);
                    *(float2*)&C[(size_t)r * ldc + col] =
                        make_float2(fast_tanh(vj.x + b0), fast_tanh(vk.x + b1));
                    *(float2*)&C[(size_t)(r + 1) * ldc + col] =
                        make_float2(fast_tanh(vj.y + b0), fast_tanh(vk.y + b1));
                }
            }
        }
    }
}

__global__ __launch_bounds__(NT_, 2)
void k_persist(const float* __restrict__ x, const int* __restrict__ ops,
               const float* __restrict__ Wd,  const float* __restrict__ bd,
               const float* __restrict__ Wl,  const float* __restrict__ bl,
               const float* __restrict__ Wr,  const float* __restrict__ br,
               const float* __restrict__ Wsd, const float* __restrict__ bsd,
               const float* __restrict__ Wsf, const float* __restrict__ bsf,
               const float* __restrict__ Wss, const float* __restrict__ bss,
               const float* __restrict__ Wbox,const float* __restrict__ bbox,
               float* __restrict__ out)
{
    const int id = blockIdx.x;
    for (int i = id * NT_ + threadIdx.x; i < B_ * F_; i += G_ * NT_)
        g_stack[0][i] = x[i];
    gsync();

    int sp = 1, bc = 0, sc = 0;
    for (int t = 0; t < L_; ++t) {
        const int op = __ldg(&ops[L_ - 1 - t]);   // processing order (row 0)
        if (op == 1) {
            gemm_tile(g_stack[sp - 1], Wd, bd, g_h, F_, H_, H_,
                      (id >> 4) * 64, (id & 15) * 64);
            gsync();
            if (id < 128)
                gemm_tile(g_h, Wl, bl, g_stack[sp - 1], H_, F_, F_,
                          (id >> 3) * 64, (id & 7) * 64);
            else
                gemm_tile(g_h, Wr, br, g_stack[sp], H_, F_, F_,
                          ((id - 128) >> 3) * 64, ((id - 128) & 7) * 64);
            gsync();
            ++sp;
        } else if (op == 2) {
            gemm_tile(g_stack[sp - 1], Wsd, bsd, g_h, F_, H_, H_,
                      (id >> 4) * 64, (id & 15) * 64);
            gsync();
            if (id < 128)
                gemm_tile(g_h, Wsf, bsf, g_stack[sp - 1], H_, F_, F_,
                          (id >> 3) * 64, (id & 7) * 64);
            else if (id < 144)
                gemm_tile(g_h, Wss, bss, g_sym[sc], H_, S_, S_,
                          (id - 128) * 64, 0);
            gsync();
            ++sc;
        } else {
            // pop: box[bc] = tanh(Wbox·top + bbox). 8 warps: 2 per row, 4 rows.
            const int wp = threadIdx.x >> 5, lane = threadIdx.x & 31;
            const int row = id * 4 + (wp >> 1);
            const float* tr = g_stack[sp - 1] + (size_t)row * F_;
            float xv[F_ / 32];
#pragma unroll
            for (int i = 0; i < F_ / 32; ++i) xv[i] = tr[lane + 32 * i];
            for (int c = (wp & 1); c < BOX_; c += 2) {
                const float* wr = Wbox + (size_t)c * F_;
                float s = 0.f;
#pragma unroll
                for (int i = 0; i < F_ / 32; ++i)
                    s = fmaf(xv[i], __ldg(&wr[lane + 32 * i]), s);
#pragma unroll
                for (int off = 16; off > 0; off >>= 1)
                    s += __shfl_xor_sync(0xffffffffu, s, off);
                if (lane == 0)
                    g_box[bc][row * BOX_ + c] = fast_tanh(s + __ldg(&bbox[c]));
            }
            ++bc; --sp;   // next phase's gsync orders these writes before emit
        }
    }
    gsync();

    // emit: boxes [B,64,12] then syms [B,64,8], reversed + zero-padded
    const int NBOX = B_ * MAXB_ * BOX_;
    const int NSYM = B_ * MAXSY_ * S_;
    for (int idx = id * NT_ + threadIdx.x; idx < NBOX + NSYM; idx += G_ * NT_) {
        if (idx < NBOX) {
            int b = idx / (MAXB_ * BOX_);
            int r = idx % (MAXB_ * BOX_);
            int j = r / BOX_, c = r % BOX_;
            out[idx] = (j < bc) ? g_box[bc - 1 - j][b * BOX_ + c] : 0.f;
        } else {
            int i2 = idx - NBOX;
            int b = i2 / (MAXSY_ * S_);
            int r = i2 % (MAXSY_ * S_);
            int j = r / S_, c = r % S_;
            out[idx] = (j < sc) ? g_sym[sc - 1 - j][b * S_ + c] : 0.f;
        }
    }
}

extern "C" void kernel_launch(void* const* d_in, const int* in_sizes, int n_in,
                              void* d_out, int out_size) {
    (void)in_sizes; (void)n_in; (void)out_size;
    k_persist<<<G_, NT_>>>(
        (const float*)d_in[0], (const int*)d_in[1],
        (const float*)d_in[2], (const float*)d_in[3],
        (const float*)d_in[4], (const float*)d_in[5],
        (const float*)d_in[6], (const float*)d_in[7],
        (const float*)d_in[8], (const float*)d_in[9],
        (const float*)d_in[10], (const float*)d_in[11],
        (const float*)d_in[12], (const float*)d_in[13],
        (const float*)d_in[14], (const float*)d_in[15],
        (float*)d_out);
}